// round 16
// baseline (speedup 1.0000x reference)
#include <cuda_runtime.h>
#include <cstdint>

// PointPillars scatter, inverted as index-map + gather (PDL-chained).
// B=4, C=64, H=512, W=512, P read from in_sizes.
//
// Init-free map: g_map holds (pid+1), 0 = empty. Zero-initialized at module
// load; gather self-cleans consumed cells so every graph replay starts from
// a clean map (gather -> next-replay scatter is stream-ordered).
//
// Champion structure (r9/r15, 62.8us) with ONE change: output stores use
// __stwt (write-through, no L2 allocation) and feature loads use default
// caching. Hypothesis: the 256 MB __stcs write stream was cycling L2 every
// replay and evicting the 100 MB feature tensor; with .wt writes the L2
// can hold feat resident across replays, cutting DRAM read traffic.
//
// Evidence matrix (rounds 5-15) — do NOT reintroduce:
//  - chunked load/store interleave (r14): MLP 16->4, 2x slower. The
//    FRONT-BATCHED 16x LDG.128 is load-bearing.
//  - block barriers after random reads (r7): catastrophic.
//  - warp-shfl load cooperation (r13), smem staging (r7/r13): slower.
//  - software grid-barrier fusion (r11): loses to PDL.
//  - ILP-4 scatter (r12): no gain.
//  - occupancy/cache/store-width changes: all neutral on the gather.
#define B_ 4
#define C_ 64
#define H_ 512
#define W_ 512
#define HW_ (H_ * W_)        // 262144 = 2^18
#define BHW_ (B_ * HW_)      // 1048576

__device__ int g_map[BHW_];  // zero-initialized at load; 0 = empty

// ---------------------------------------------------------------------------
// Kernel 1: scatter (pid+1) per pillar. atomicMax => highest pillar index
// wins == the reference's sequential last-write-wins.
__global__ void __launch_bounds__(512) k_scatter_idx(const int* __restrict__ coords, int P) {
    int p = blockIdx.x * blockDim.x + threadIdx.x;
    if (p < P) {
        int4 c = __ldcs(reinterpret_cast<const int4*>(coords) + p);  // [b,z,y,x]
        int b = c.x, y = c.z, x = c.w;
        if ((unsigned)y < H_ && (unsigned)x < W_) {
            atomicMax(&g_map[(b * H_ + y) * W_ + x], p + 1);
        }
    }
    cudaTriggerProgrammaticLaunchCompletion();
}

// ---------------------------------------------------------------------------
// Kernel 2: gather + self-clean. One thread per BEV cell owns all 64
// channels: 16x float4 contiguous feature-row reads FRONT-BATCHED (MLP=16,
// default cache policy -> L2-resident across replays), then 64 strided
// channel stores coalesced across the warp in w, written with __stwt so
// the output stream does not occupy L2. No smem, no barriers.
__global__ void __launch_bounds__(256) k_gather(const float* __restrict__ feat,
                                                float* __restrict__ out) {
    int s = blockIdx.x * blockDim.x + threadIdx.x;   // 0 .. BHW_-1
    int b  = s >> 18;            // / HW_
    int sp = s & (HW_ - 1);      // within-batch spatial index

    // Overlaps the PDL dependency wait below.
    float* op = out + (size_t)b * (C_ * HW_) + sp;
    int*   mp = &g_map[s];

    cudaGridDependencySynchronize();   // scatter grid fully complete

    int v = *mp;

    float4 r[16];
    if (v > 0) {
        *mp = 0;                 // self-clean for next graph replay
        const float4* fp = reinterpret_cast<const float4*>(feat + (size_t)(v - 1) * C_);
#pragma unroll
        for (int i = 0; i < 16; i++) r[i] = fp[i];   // default: L2-cacheable
    } else {
#pragma unroll
        for (int i = 0; i < 16; i++) r[i] = make_float4(0.f, 0.f, 0.f, 0.f);
    }

#pragma unroll
    for (int i = 0; i < 16; i++) {
        __stwt(op + (size_t)(4 * i + 0) * HW_, r[i].x);
        __stwt(op + (size_t)(4 * i + 1) * HW_, r[i].y);
        __stwt(op + (size_t)(4 * i + 2) * HW_, r[i].z);
        __stwt(op + (size_t)(4 * i + 3) * HW_, r[i].w);
    }
}

// ---------------------------------------------------------------------------
extern "C" void kernel_launch(void* const* d_in, const int* in_sizes, int n_in,
                              void* d_out, int out_size) {
    const float* feat   = (const float*)d_in[0];   // [P, C] float32
    const int*   coords = (const int*)d_in[1];     // [P, 4] int32
    int P = in_sizes[1] / 4;

    k_scatter_idx<<<(P + 511) / 512, 512>>>(coords, P);

    // Gather with programmatic dependent launch on the scatter.
    cudaLaunchConfig_t cfg = {};
    cfg.gridDim  = dim3(BHW_ / 256);
    cfg.blockDim = dim3(256);
    cfg.stream   = 0;  // capture stream
    cudaLaunchAttribute attr[1];
    attr[0].id = cudaLaunchAttributeProgrammaticStreamSerialization;
    attr[0].val.programmaticStreamSerializationAllowed = 1;
    cfg.attrs    = attr;
    cfg.numAttrs = 1;
    cudaLaunchKernelEx(&cfg, k_gather, feat, (float*)d_out);
}

// round 17
// speedup vs baseline: 1.0653x; 1.0653x over previous
#include <cuda_runtime.h>
#include <cstdint>

// PointPillars scatter, inverted as index-map + gather (PDL-chained).
// B=4, C=64, H=512, W=512, P read from in_sizes.
//
// Init-free map: g_map holds (pid+1), 0 = empty. Zero-initialized at module
// load; gather self-cleans consumed cells so every graph replay starts from
// a clean map (gather -> next-replay scatter is stream-ordered).
//
// FINAL FORM (champion, 62.8us). Complete evidence matrix, rounds 5-16:
//  - gather floor ~58-59us at DRAM ~65% (≈351 MB mixed random-read +
//    streaming-write at ~6 TB/s effective). Invariant to occupancy
//    (30-89%), cache policy, store width, and thread mapping.
//  - FRONT-BATCHED 16x LDG.128 is load-bearing: chunked load/store
//    interleave (r14) collapsed MLP 16->4 and doubled runtime.
//  - __stcs output is optimal: __stwt (r16) drains into the next replay
//    (+4.5us total); default-cached writes (r8) no better. feat does NOT
//    stay L2-resident across replays under any policy (r8, r16).
//  - block barriers after the random reads are catastrophic (r7);
//    warp-shfl load cooperation (r13) and smem staging (r7, r13) lose;
//    software grid-barrier fusion (r11) loses to PDL; ILP-4 scatter (r12)
//    loses. Do not reintroduce any of these.
#define B_ 4
#define C_ 64
#define H_ 512
#define W_ 512
#define HW_ (H_ * W_)        // 262144 = 2^18
#define BHW_ (B_ * HW_)      // 1048576

__device__ int g_map[BHW_];  // zero-initialized at load; 0 = empty

// ---------------------------------------------------------------------------
// Kernel 1: scatter (pid+1) per pillar. atomicMax => highest pillar index
// wins == the reference's sequential last-write-wins.
__global__ void __launch_bounds__(512) k_scatter_idx(const int* __restrict__ coords, int P) {
    int p = blockIdx.x * blockDim.x + threadIdx.x;
    if (p < P) {
        int4 c = __ldcs(reinterpret_cast<const int4*>(coords) + p);  // [b,z,y,x]
        int b = c.x, y = c.z, x = c.w;
        if ((unsigned)y < H_ && (unsigned)x < W_) {
            atomicMax(&g_map[(b * H_ + y) * W_ + x], p + 1);
        }
    }
    cudaTriggerProgrammaticLaunchCompletion();
}

// ---------------------------------------------------------------------------
// Kernel 2: gather + self-clean. One thread per BEV cell owns all 64
// channels: 16x float4 contiguous feature-row reads FRONT-BATCHED (MLP=16,
// streaming), then 64 strided channel stores coalesced across the warp in
// w (streaming). Address math overlaps the PDL wait. No smem, no barriers.
__global__ void __launch_bounds__(256) k_gather(const float* __restrict__ feat,
                                                float* __restrict__ out) {
    int s = blockIdx.x * blockDim.x + threadIdx.x;   // 0 .. BHW_-1
    int b  = s >> 18;            // / HW_
    int sp = s & (HW_ - 1);      // within-batch spatial index

    // Overlaps the PDL dependency wait below.
    float* op = out + (size_t)b * (C_ * HW_) + sp;
    int*   mp = &g_map[s];

    cudaGridDependencySynchronize();   // scatter grid fully complete

    int v = *mp;

    float4 r[16];
    if (v > 0) {
        *mp = 0;                 // self-clean for next graph replay
        const float4* fp = reinterpret_cast<const float4*>(feat + (size_t)(v - 1) * C_);
#pragma unroll
        for (int i = 0; i < 16; i++) r[i] = __ldcs(fp + i);
    } else {
#pragma unroll
        for (int i = 0; i < 16; i++) r[i] = make_float4(0.f, 0.f, 0.f, 0.f);
    }

#pragma unroll
    for (int i = 0; i < 16; i++) {
        __stcs(op + (size_t)(4 * i + 0) * HW_, r[i].x);
        __stcs(op + (size_t)(4 * i + 1) * HW_, r[i].y);
        __stcs(op + (size_t)(4 * i + 2) * HW_, r[i].z);
        __stcs(op + (size_t)(4 * i + 3) * HW_, r[i].w);
    }
}

// ---------------------------------------------------------------------------
extern "C" void kernel_launch(void* const* d_in, const int* in_sizes, int n_in,
                              void* d_out, int out_size) {
    const float* feat   = (const float*)d_in[0];   // [P, C] float32
    const int*   coords = (const int*)d_in[1];     // [P, 4] int32
    int P = in_sizes[1] / 4;

    k_scatter_idx<<<(P + 511) / 512, 512>>>(coords, P);

    // Gather with programmatic dependent launch on the scatter.
    cudaLaunchConfig_t cfg = {};
    cfg.gridDim  = dim3(BHW_ / 256);
    cfg.blockDim = dim3(256);
    cfg.stream   = 0;  // capture stream
    cudaLaunchAttribute attr[1];
    attr[0].id = cudaLaunchAttributeProgrammaticStreamSerialization;
    attr[0].val.programmaticStreamSerializationAllowed = 1;
    cfg.attrs    = attr;
    cfg.numAttrs = 1;
    cudaLaunchKernelEx(&cfg, k_gather, feat, (float*)d_out);
}